// round 2
// baseline (speedup 1.0000x reference)
#include <cuda_runtime.h>
#include <math.h>

typedef unsigned long long ull;

// Problem constants
#define NB 8
#define SQ 4096
#define EE 1024
#define HH 16
#define BH (NB*HH)       // 128
#define NCHUNK 32
#define CHUNK 128

// Scratch (static device globals -- allocation-free per harness rules)
__device__ float g_wqk[HH*EE];
__device__ float g_c[HH];
__device__ float g_logits[BH*SQ];
__device__ float g_pm[BH*SQ];
__device__ float g_A[BH*SQ];
__device__ float g_psum[BH];
__device__ float g_partial[NB*NCHUNK*HH*EE];   // 16 MB partial ctx
__device__ float g_ctx[NB*HH*EE];
__device__ float g_hidden[NB*EE];
__device__ float g_hl[NB*EE];
__device__ float g_act[NB*4*EE];

__device__ __forceinline__ float warp_sum(float v){
    #pragma unroll
    for (int o=16;o;o>>=1) v += __shfl_xor_sync(0xffffffffu, v, o);
    return v;
}

// packed f32x2 helpers (FFMA2 path -- full-rate fp32 on sm_103a)
__device__ __forceinline__ void ffma2(ull &d, ull a, ull b){
    asm("fma.rn.f32x2 %0, %1, %2, %0;" : "+l"(d) : "l"(a), "l"(b));
}
__device__ __forceinline__ ull fadd2(ull a, ull b){
    ull d; asm("add.rn.f32x2 %0, %1, %2;" : "=l"(d) : "l"(a), "l"(b)); return d;
}
__device__ __forceinline__ ull pk2(float x, float y){
    float2 t = make_float2(x,y); return *(ull*)&t;
}
__device__ __forceinline__ float2 upk(ull v){ return *(float2*)&v; }

// ---------------- K0: per-head q projection + folded w_qk ----------------
// block h: qv[d] = (Wq[h*64+d,:]·query + bq), then
// w_qk[h,e] = 0.125 * sum_d qv[d]*Wk[h*64+d,e];  c[h] = 0.125*qv·bk_h
__global__ void __launch_bounds__(256) k_wqk(const float4* __restrict__ Wq4,
                                             const float4* __restrict__ q4,
                                             const float*  __restrict__ bq,
                                             const float4* __restrict__ Wk4,
                                             const float*  __restrict__ bk){
    __shared__ float qv[64];
    int h = blockIdx.x, tid = threadIdx.x;
    {   // 64 rows x 4 threads
        int r = tid>>2, c4 = tid&3;
        int row = h*64 + r;
        float acc = 0.f;
        #pragma unroll 8
        for (int j=0;j<64;j++){
            float4 w = Wq4[row*256 + c4*64 + j];
            float4 q = q4[c4*64 + j];
            acc += w.x*q.x + w.y*q.y + w.z*q.z + w.w*q.w;
        }
        acc += __shfl_xor_sync(0xffffffffu, acc, 1);
        acc += __shfl_xor_sync(0xffffffffu, acc, 2);
        if (c4==0) qv[r] = acc + bq[row];
    }
    __syncthreads();
    float4 acc = make_float4(0.f,0.f,0.f,0.f);
    #pragma unroll 8
    for (int d=0; d<64; d++){
        float w = qv[d];
        float4 kk = Wk4[(h*64+d)*256 + tid];
        acc.x += w*kk.x; acc.y += w*kk.y; acc.z += w*kk.z; acc.w += w*kk.w;
    }
    acc.x*=0.125f; acc.y*=0.125f; acc.z*=0.125f; acc.w*=0.125f;
    ((float4*)g_wqk)[h*256+tid] = acc;
    if (tid==0){
        float c=0.f;
        for (int d=0;d<64;d++) c += qv[d]*bk[h*64+d];
        g_c[h] = 0.125f*c;
    }
}

// ---------------- K1: logits[b,h,s] = w_qk[h]·x[b,s] + c[h] (pass 1 over x) ----------------
// 8 warps: (e-half eh) x (head-quartet hq). w_qk register-resident as f32x2.
// 4-row tiles; smem-transpose reduction (no 5-level shuffles).
__global__ void __launch_bounds__(256) k_logits(const float4* __restrict__ x4){
    __shared__ float4 sx[4*256];      // 16KB: 4 rows x 1024 floats
    __shared__ ull    part[16*256];   // 32KB: packed partials [acc][tid]
    int tid = threadIdx.x, lane = tid&31, warp = tid>>5;
    int eh = warp>>2, hq = warp&3;
    const float4* w4 = (const float4*)g_wqk;
    ull w[4][4][2];
    #pragma unroll
    for (int hp=0;hp<4;hp++)
        #pragma unroll
        for (int st=0;st<4;st++){
            float4 t = w4[(hq*4+hp)*256 + eh*128 + st*32 + lane];
            w[hp][st][0] = pk2(t.x,t.y);
            w[hp][st][1] = pk2(t.z,t.w);
        }
    // phase-2 constants for this thread
    int o = tid>>2, k = tid&3;
    int oi = o>>4, oh = o&15;
    int ohq = oh>>2, ohp = oh&3;
    int aidx = oi*4 + ohp;
    int w0 = (k<2) ? ohq : (ohq+4);
    int rbase2 = aidx*256 + w0*32 + (k&1)*16;

    int rowbase = blockIdx.x*32;
    for (int t8=0;t8<8;t8++){
        int rb = rowbase + t8*4;
        #pragma unroll
        for (int i=0;i<4;i++) sx[i*256+tid] = x4[(rb+i)*256 + tid];
        __syncthreads();
        ull a[16];
        #pragma unroll
        for (int j=0;j<16;j++) a[j] = pk2(0.f,0.f);
        #pragma unroll
        for (int i=0;i<4;i++){
            #pragma unroll
            for (int st=0;st<4;st++){
                float4 xv = sx[i*256 + eh*128 + st*32 + lane];
                ull x01 = pk2(xv.x,xv.y), x23 = pk2(xv.z,xv.w);
                #pragma unroll
                for (int hp=0;hp<4;hp++){
                    ffma2(a[i*4+hp], w[hp][st][0], x01);
                    ffma2(a[i*4+hp], w[hp][st][1], x23);
                }
            }
        }
        #pragma unroll
        for (int j=0;j<16;j++) part[j*256+tid] = a[j];
        __syncthreads();
        // phase 2: 64 outputs (row i, head h), 4 threads each summing 16 lanes
        {
            const ull* p = part + rbase2;
            ull s0 = fadd2(p[0], p[1]),  s1 = fadd2(p[2], p[3]);
            ull s2 = fadd2(p[4], p[5]),  s3 = fadd2(p[6], p[7]);
            ull s4 = fadd2(p[8], p[9]),  s5 = fadd2(p[10],p[11]);
            ull s6 = fadd2(p[12],p[13]), s7 = fadd2(p[14],p[15]);
            ull s = fadd2(fadd2(fadd2(s0,s1),fadd2(s2,s3)),
                          fadd2(fadd2(s4,s5),fadd2(s6,s7)));
            float2 f = upk(s);
            float v = f.x + f.y;
            v += __shfl_xor_sync(0xffffffffu, v, 1);
            v += __shfl_xor_sync(0xffffffffu, v, 2);
            if (k==0){
                int r = rb + oi, b = r>>12, ss = r&4095;
                g_logits[((b<<4)+oh)*4096 + ss] = v + g_c[oh];
            }
        }
        __syncthreads();
    }
}

// ---------------- K2: softmax over S + gumbel hard mask, per (b,h) ----------------
__global__ void __launch_bounds__(256) k_softmax(const float2* __restrict__ gu2){
    __shared__ float red[8];
    __shared__ float bc;
    int bid = blockIdx.x;                 // b*16+h
    int tid = threadIdx.x, lane = tid&31, warp = tid>>5;
    int base = bid*4096;
    float l[16];
    float m = -1e30f;
    #pragma unroll
    for (int j=0;j<16;j++){ l[j] = g_logits[base + tid + 256*j]; m = fmaxf(m, l[j]); }
    #pragma unroll
    for (int o=16;o;o>>=1) m = fmaxf(m, __shfl_xor_sync(0xffffffffu,m,o));
    if (lane==0) red[warp]=m;
    __syncthreads();
    if (tid==0){ float mm=red[0]; for(int i=1;i<8;i++) mm=fmaxf(mm,red[i]); bc=mm; }
    __syncthreads();
    m = bc;
    float ex[16]; float sum=0.f;
    #pragma unroll
    for (int j=0;j<16;j++){ ex[j]=__expf(l[j]-m); sum+=ex[j]; }
    sum = warp_sum(sum);
    if (lane==0) red[warp]=sum;
    __syncthreads();
    if (tid==0){ float ss=0.f; for(int i=0;i<8;i++) ss+=red[i]; bc=ss; }
    __syncthreads();
    float inv = 1.f/bc;
    float ps=0.f;
    #pragma unroll
    for (int j=0;j<16;j++){
        int s = tid+256*j;
        float prob = ex[j]*inv;
        float2 u = gu2[base+s];
        float g0 = -__logf(-__logf(u.x+1e-20f)+1e-20f);
        float g1 = -__logf(-__logf(u.y+1e-20f)+1e-20f);
        float A = (l[j]+g1 > g0) ? 1.f : 0.f;
        float pm = A*prob;
        g_A[base+s]=A; g_pm[base+s]=pm; ps+=pm;
    }
    ps = warp_sum(ps);
    if (lane==0) red[warp]=ps;
    __syncthreads();
    if (tid==0){ float ss=0.f; for(int i=0;i<8;i++) ss+=red[i]; g_psum[bid]=ss; }
}

// ---------------- K2b: masks/attn = sum over heads ----------------
__global__ void __launch_bounds__(256) k_sums(float* __restrict__ out){
    int idx = blockIdx.x*256 + threadIdx.x;    // b*4096+s
    int b = idx>>12, s = idx&4095;
    float ms=0.f, as=0.f;
    #pragma unroll
    for (int h=0;h<16;h++){
        int off = ((b<<4)+h)*4096 + s;
        ms += g_A[off];
        as += g_pm[off];
    }
    out[8192+idx] = ms;
    out[8192+32768+idx] = as;
}

// ---------------- K3: ctx partials (pass 2 over x), f32x2 ----------------
__global__ void __launch_bounds__(256) k_ctx(const float4* __restrict__ x4){
    __shared__ float2 spm[16*128];   // (p,p) duplicated for packed FMA
    int tid = threadIdx.x;
    int b = blockIdx.x >> 5, chunk = blockIdx.x & 31;
    int s0 = chunk*CHUNK;
    #pragma unroll
    for (int i=0;i<8;i++){
        int idx = tid + 256*i;
        int h = idx>>7, si = idx&127;
        float p = g_pm[((b<<4)+h)*4096 + s0 + si];
        spm[idx] = make_float2(p,p);
    }
    __syncthreads();
    ull acc[16][2];
    #pragma unroll
    for (int h=0;h<16;h++){ acc[h][0]=pk2(0.f,0.f); acc[h][1]=pk2(0.f,0.f); }
    #pragma unroll 2
    for (int si=0; si<CHUNK; si++){
        float4 xv = x4[(b*4096 + s0 + si)*256 + tid];
        ull x01 = pk2(xv.x,xv.y), x23 = pk2(xv.z,xv.w);
        #pragma unroll
        for (int h=0;h<16;h++){
            ull p = *(ull*)&spm[h*128+si];
            ffma2(acc[h][0], p, x01);
            ffma2(acc[h][1], p, x23);
        }
    }
    float4* p4 = (float4*)g_partial;
    #pragma unroll
    for (int h=0;h<16;h++){
        float2 lo = upk(acc[h][0]), hi = upk(acc[h][1]);
        p4[((b*32+chunk)*16 + h)*256 + tid] = make_float4(lo.x,lo.y,hi.x,hi.y);
    }
}

// ---------------- K3r: deterministic reduction of ctx partials ----------------
__global__ void __launch_bounds__(256) k_ctxr(){
    int idx = blockIdx.x*256 + threadIdx.x;   // b*16384 + (h*1024+e)
    int b = idx>>14, rem = idx & 16383;
    float s=0.f;
    #pragma unroll
    for (int c=0;c<32;c++) s += g_partial[((b*32+c)<<14) + rem];
    g_ctx[idx] = s;
}

// ---------------- K4a: hidden = Wv·ctx + bv*psum ----------------
__global__ void __launch_bounds__(256) k_hidden(const float4* __restrict__ Wv4,
                                                const float*  __restrict__ bv){
    int lane = threadIdx.x&31, warp = threadIdx.x>>5;
    int row = blockIdx.x*8+warp;
    int h = row>>6;
    float4 w[8];
    #pragma unroll
    for (int k=0;k<8;k++) w[k] = Wv4[row*256 + lane + 32*k];
    const float4* c4 = (const float4*)g_ctx;
    float acc[8];
    #pragma unroll
    for (int b=0;b<8;b++){
        float s=0.f;
        #pragma unroll
        for (int k=0;k<8;k++){
            float4 c = c4[((b<<4)+h)*256 + lane + 32*k];
            s += w[k].x*c.x + w[k].y*c.y + w[k].z*c.z + w[k].w*c.w;
        }
        acc[b]=s;
    }
    #pragma unroll
    for (int o=16;o;o>>=1)
        #pragma unroll
        for (int b=0;b<8;b++) acc[b] += __shfl_xor_sync(0xffffffffu, acc[b], o);
    if (lane==0){
        float bvr = bv[row];
        #pragma unroll
        for (int b=0;b<8;b++) g_hidden[b*1024+row] = acc[b] + bvr*g_psum[(b<<4)+h];
    }
}

// ---------------- K4b: LayerNorm (biased var, eps=1e-5) ----------------
__global__ void __launch_bounds__(256) k_ln(const float* __restrict__ lg,
                                            const float* __restrict__ lb){
    __shared__ float red[8]; __shared__ float bc;
    int b = blockIdx.x, tid = threadIdx.x, lane=tid&31, warp=tid>>5;
    float v[4];
    #pragma unroll
    for (int j=0;j<4;j++) v[j] = g_hidden[b*1024 + tid + 256*j];
    float s = v[0]+v[1]+v[2]+v[3];
    s = warp_sum(s); if (lane==0) red[warp]=s; __syncthreads();
    if (tid==0){ float t=0.f; for(int i=0;i<8;i++)t+=red[i]; bc=t*(1.f/1024.f);} __syncthreads();
    float mu = bc;
    float q=0.f;
    #pragma unroll
    for (int j=0;j<4;j++){ float d=v[j]-mu; q+=d*d; }
    q = warp_sum(q); if(lane==0) red[warp]=q; __syncthreads();
    if (tid==0){ float t=0.f; for(int i=0;i<8;i++)t+=red[i]; bc=rsqrtf(t*(1.f/1024.f)+1e-5f);} __syncthreads();
    float rstd = bc;
    #pragma unroll
    for (int j=0;j<4;j++){
        int i = tid+256*j;
        g_hl[b*1024+i] = (v[j]-mu)*rstd*lg[i] + lb[i];
    }
}

// ---------------- K4c: act = relu(hl @ W1^T + b1) ----------------
__global__ void __launch_bounds__(256) k_mlp1(const float4* __restrict__ W14,
                                              const float*  __restrict__ b1){
    __shared__ float4 hls[2048];   // 8x1024 floats
    int tid = threadIdx.x, lane=tid&31, warp=tid>>5;
    const float4* h4 = (const float4*)g_hl;
    #pragma unroll
    for (int i=0;i<8;i++) hls[tid + 256*i] = h4[tid+256*i];
    __syncthreads();
    int row = blockIdx.x*8+warp;
    float4 w[8];
    #pragma unroll
    for (int k=0;k<8;k++) w[k]=W14[row*256+lane+32*k];
    float acc[8];
    #pragma unroll
    for (int b=0;b<8;b++){
        float s=0.f;
        #pragma unroll
        for (int k=0;k<8;k++){
            float4 hv = hls[b*256 + lane + 32*k];
            s += w[k].x*hv.x + w[k].y*hv.y + w[k].z*hv.z + w[k].w*hv.w;
        }
        acc[b]=s;
    }
    #pragma unroll
    for (int o=16;o;o>>=1)
        #pragma unroll
        for (int b=0;b<8;b++) acc[b] += __shfl_xor_sync(0xffffffffu, acc[b], o);
    if (lane==0){
        float bb = b1[row];
        #pragma unroll
        for (int b=0;b<8;b++) g_act[b*4096+row] = fmaxf(acc[b]+bb, 0.f);
    }
}

// ---------------- K4d: out = act @ W2^T + b2 ----------------
__global__ void __launch_bounds__(256) k_mlp2(const float4* __restrict__ W24,
                                              const float*  __restrict__ b2,
                                              float* __restrict__ out){
    extern __shared__ float4 as4[];    // 8x4096 floats = 128KB dynamic
    int tid=threadIdx.x, lane=tid&31, warp=tid>>5;
    const float4* a4 = (const float4*)g_act;
    #pragma unroll
    for (int i=0;i<32;i++) as4[tid+256*i] = a4[tid+256*i];
    __syncthreads();
    int row = blockIdx.x*8+warp;
    float acc[8];
    #pragma unroll
    for (int b=0;b<8;b++) acc[b]=0.f;
    #pragma unroll 4
    for (int k=0;k<32;k++){
        float4 w = W24[row*1024 + lane + 32*k];
        #pragma unroll
        for (int b=0;b<8;b++){
            float4 av = as4[b*1024 + lane + 32*k];
            acc[b] += w.x*av.x + w.y*av.y + w.z*av.z + w.w*av.w;
        }
    }
    #pragma unroll
    for (int o=16;o;o>>=1)
        #pragma unroll
        for (int b=0;b<8;b++) acc[b] += __shfl_xor_sync(0xffffffffu, acc[b], o);
    if (lane==0){
        float bb = b2[row];
        #pragma unroll
        for (int b=0;b<8;b++) out[b*1024+row] = acc[b] + bb;
    }
}

extern "C" void kernel_launch(void* const* d_in, const int* in_sizes, int n_in,
                              void* d_out, int out_size){
    const float* x     = (const float*)d_in[0];
    const float* gu    = (const float*)d_in[1];
    const float* query = (const float*)d_in[2];
    const float* Wq    = (const float*)d_in[3];
    const float* bq    = (const float*)d_in[4];
    const float* Wk    = (const float*)d_in[5];
    const float* bk    = (const float*)d_in[6];
    const float* Wv    = (const float*)d_in[7];
    const float* bv    = (const float*)d_in[8];
    const float* ln_g  = (const float*)d_in[9];
    const float* ln_b  = (const float*)d_in[10];
    const float* W1    = (const float*)d_in[11];
    const float* b1    = (const float*)d_in[12];
    const float* W2    = (const float*)d_in[13];
    const float* b2    = (const float*)d_in[14];
    float* out = (float*)d_out;

    cudaFuncSetAttribute(k_mlp2, cudaFuncAttributeMaxDynamicSharedMemorySize, 131072);

    k_wqk    <<<16,256>>>((const float4*)Wq, (const float4*)query, bq,
                          (const float4*)Wk, bk);
    k_logits <<<1024,256>>>((const float4*)x);
    k_softmax<<<128,256>>>((const float2*)gu);
    k_sums   <<<128,256>>>(out);
    k_ctx    <<<256,256>>>((const float4*)x);
    k_ctxr   <<<512,256>>>();
    k_hidden <<<128,256>>>((const float4*)Wv, bv);
    k_ln     <<<8,256>>>(ln_g, ln_b);
    k_mlp1   <<<512,256>>>((const float4*)W1, b1);
    k_mlp2   <<<128,256,131072>>>((const float4*)W2, b2, out);
}

// round 3
// speedup vs baseline: 1.3258x; 1.3258x over previous
#include <cuda_runtime.h>
#include <math.h>

typedef unsigned long long ull;

// Problem constants
#define NB 8
#define SQ 4096
#define EE 1024
#define HH 16
#define BH (NB*HH)       // 128
#define NCHUNK 32
#define CHUNK 128

// Scratch (static device globals -- allocation-free per harness rules)
__device__ float g_wqk[HH*EE];
__device__ float g_c[HH];
__device__ float g_logits[BH*SQ];
__device__ float g_pm[BH*SQ];
__device__ float g_A[BH*SQ];
__device__ float g_psum[BH];
__device__ float g_partial[NB*NCHUNK*HH*EE];   // 16 MB partial ctx
__device__ float g_ctx[NB*HH*EE];
__device__ float g_hidden[NB*EE];
__device__ float g_hl[NB*EE];
__device__ float g_act[NB*4*EE];

__device__ __forceinline__ float warp_sum(float v){
    #pragma unroll
    for (int o=16;o;o>>=1) v += __shfl_xor_sync(0xffffffffu, v, o);
    return v;
}

// packed f32x2 helpers (FFMA2 path on sm_103a)
__device__ __forceinline__ void ffma2(ull &d, ull a, ull b){
    asm("fma.rn.f32x2 %0, %1, %2, %0;" : "+l"(d) : "l"(a), "l"(b));
}
__device__ __forceinline__ ull pk2(float x, float y){
    float2 t = make_float2(x,y); return *(ull*)&t;
}
__device__ __forceinline__ float2 upk(ull v){ return *(float2*)&v; }

// ---------------- K0: per-head q projection + folded w_qk ----------------
__global__ void __launch_bounds__(256) k_wqk(const float4* __restrict__ Wq4,
                                             const float4* __restrict__ q4,
                                             const float*  __restrict__ bq,
                                             const float4* __restrict__ Wk4,
                                             const float*  __restrict__ bk){
    __shared__ float qv[64];
    int h = blockIdx.x, tid = threadIdx.x;
    {   // 64 rows x 4 threads
        int r = tid>>2, c4 = tid&3;
        int row = h*64 + r;
        float acc = 0.f;
        #pragma unroll 8
        for (int j=0;j<64;j++){
            float4 w = Wq4[row*256 + c4*64 + j];
            float4 q = q4[c4*64 + j];
            acc += w.x*q.x + w.y*q.y + w.z*q.z + w.w*q.w;
        }
        acc += __shfl_xor_sync(0xffffffffu, acc, 1);
        acc += __shfl_xor_sync(0xffffffffu, acc, 2);
        if (c4==0) qv[r] = acc + bq[row];
    }
    __syncthreads();
    float4 acc = make_float4(0.f,0.f,0.f,0.f);
    #pragma unroll 8
    for (int d=0; d<64; d++){
        float w = qv[d];
        float4 kk = Wk4[(h*64+d)*256 + tid];
        acc.x += w*kk.x; acc.y += w*kk.y; acc.z += w*kk.z; acc.w += w*kk.w;
    }
    acc.x*=0.125f; acc.y*=0.125f; acc.z*=0.125f; acc.w*=0.125f;
    ((float4*)g_wqk)[h*256+tid] = acc;
    if (tid==0){
        float c=0.f;
        for (int d=0;d<64;d++) c += qv[d]*bk[h*64+d];
        g_c[h] = 0.125f*c;
    }
}

// ---------------- K1: logits = w_qk·x + c  (pass 1 over x) ----------------
// 8 warps = 2 e-halves x 4 head-quartets. 8-row tiles. w staged in smem.
// Packed f32x2 FMA; register butterfly fold (value j -> lane j); tiny smem
// handoff to combine e-halves.
__global__ void __launch_bounds__(256,2) k_logits(const float4* __restrict__ x4){
    __shared__ float4 sx[8*256];       // 32KB: 8 rows x 1024 floats
    __shared__ float  sw[HH*EE];       // 64KB: all of w_qk
    __shared__ float  sred[4*32];
    int tid = threadIdx.x, lane = tid&31, warp = tid>>5;
    int eh = warp>>2, hq = warp&3;
    {
        const float4* w4 = (const float4*)g_wqk;
        float4* sw4 = (float4*)sw;
        #pragma unroll
        for (int i=0;i<16;i++) sw4[tid + 256*i] = w4[tid + 256*i];
    }
    float ch = g_c[hq*4 + (lane&3)];
    __syncthreads();
    const ull* swu = (const ull*)sw;
    int rowbase = blockIdx.x*32;
    int b = rowbase>>12;
    for (int t8=0;t8<4;t8++){
        int rb = rowbase + t8*8;
        #pragma unroll
        for (int i=0;i<8;i++) sx[i*256+tid] = x4[(rb+i)*256 + tid];
        __syncthreads();
        ull a[32];
        #pragma unroll
        for (int j=0;j<32;j++) a[j] = 0ULL;
        #pragma unroll
        for (int st=0; st<4; st++){
            ull w0[4], w1[4];
            #pragma unroll
            for (int hp=0;hp<4;hp++){
                int e = eh*512 + st*128 + lane*4;
                int p = ((hq*4+hp)*1024 + e)>>1;
                w0[hp] = swu[p];
                w1[hp] = swu[p+1];
            }
            #pragma unroll
            for (int i=0;i<8;i++){
                float4 xv = sx[i*256 + eh*128 + st*32 + lane];
                ull x01 = pk2(xv.x,xv.y), x23 = pk2(xv.z,xv.w);
                #pragma unroll
                for (int hp=0;hp<4;hp++){
                    ffma2(a[i*4+hp], w0[hp], x01);
                    ffma2(a[i*4+hp], w1[hp], x23);
                }
            }
        }
        float v[32];
        #pragma unroll
        for (int j=0;j<32;j++){ float2 f = upk(a[j]); v[j] = f.x + f.y; }
        // fold: after this, lane L holds sum over lanes of original v[L]
        #pragma unroll
        for (int s=16; s>0; s>>=1){
            #pragma unroll
            for (int j=0;j<s;j++){
                float t = (lane & s) ? v[j] : v[j+s];
                t = __shfl_xor_sync(0xffffffffu, t, s);
                v[j] = ((lane & s) ? v[j+s] : v[j]) + t;
            }
        }
        // lane L: row rb+(L>>2), head hq*4+(L&3)
        if (eh==0) sred[hq*32 + lane] = v[0];
        __syncthreads();
        if (eh==1){
            float val = v[0] + sred[hq*32 + lane] + ch;
            int row = rb + (lane>>2);
            int h = hq*4 + (lane&3);
            g_logits[((b<<4)+h)*4096 + (row & 4095)] = val;
        }
        __syncthreads();
    }
}

// ---------------- K2: softmax over S + gumbel hard mask, per (b,h) ----------------
__global__ void __launch_bounds__(256) k_softmax(const float2* __restrict__ gu2){
    __shared__ float red[8];
    __shared__ float bc;
    int bid = blockIdx.x;                 // b*16+h
    int tid = threadIdx.x, lane = tid&31, warp = tid>>5;
    int base = bid*4096;
    float l[16];
    float m = -1e30f;
    #pragma unroll
    for (int j=0;j<16;j++){ l[j] = g_logits[base + tid + 256*j]; m = fmaxf(m, l[j]); }
    #pragma unroll
    for (int o=16;o;o>>=1) m = fmaxf(m, __shfl_xor_sync(0xffffffffu,m,o));
    if (lane==0) red[warp]=m;
    __syncthreads();
    if (tid==0){ float mm=red[0]; for(int i=1;i<8;i++) mm=fmaxf(mm,red[i]); bc=mm; }
    __syncthreads();
    m = bc;
    float ex[16]; float sum=0.f;
    #pragma unroll
    for (int j=0;j<16;j++){ ex[j]=__expf(l[j]-m); sum+=ex[j]; }
    sum = warp_sum(sum);
    if (lane==0) red[warp]=sum;
    __syncthreads();
    if (tid==0){ float ss=0.f; for(int i=0;i<8;i++) ss+=red[i]; bc=ss; }
    __syncthreads();
    float inv = 1.f/bc;
    float ps=0.f;
    #pragma unroll
    for (int j=0;j<16;j++){
        int s = tid+256*j;
        float prob = ex[j]*inv;
        float2 u = gu2[base+s];
        float g0 = -__logf(-__logf(u.x+1e-20f)+1e-20f);
        float g1 = -__logf(-__logf(u.y+1e-20f)+1e-20f);
        float A = (l[j]+g1 > g0) ? 1.f : 0.f;
        float pm = A*prob;
        g_A[base+s]=A; g_pm[base+s]=pm; ps+=pm;
    }
    ps = warp_sum(ps);
    if (lane==0) red[warp]=ps;
    __syncthreads();
    if (tid==0){ float ss=0.f; for(int i=0;i<8;i++) ss+=red[i]; g_psum[bid]=ss; }
}

// ---------------- K2b: masks/attn = sum over heads (h-halves split) ----------------
__global__ void __launch_bounds__(256) k_sums(float* __restrict__ out){
    __shared__ float sA[128], sP[128];
    int tid = threadIdx.x;
    int t = tid&127, half = tid>>7;
    int sbase = blockIdx.x*128;          // global b*4096+s base
    int b = sbase>>12;
    int s = (sbase&4095) + t;
    float ms=0.f, as=0.f;
    #pragma unroll
    for (int hh=0; hh<8; hh++){
        int h = half*8 + hh;
        int off = ((b<<4)+h)*4096 + s;
        ms += g_A[off];
        as += g_pm[off];
    }
    if (half==1){ sA[t]=ms; sP[t]=as; }
    __syncthreads();
    if (half==0){
        ms += sA[t]; as += sP[t];
        out[8192 + sbase + t] = ms;
        out[8192+32768 + sbase + t] = as;
    }
}

// ---------------- K3: ctx partials (pass 2 over x), f32x2 ----------------
__global__ void __launch_bounds__(256,2) k_ctx(const float4* __restrict__ x4){
    __shared__ float2 spm[16*128];   // (p,p) duplicated for packed FMA
    int tid = threadIdx.x;
    int b = blockIdx.x >> 5, chunk = blockIdx.x & 31;
    int s0 = chunk*CHUNK;
    #pragma unroll
    for (int i=0;i<8;i++){
        int idx = tid + 256*i;
        int h = idx>>7, si = idx&127;
        float p = g_pm[((b<<4)+h)*4096 + s0 + si];
        spm[idx] = make_float2(p,p);
    }
    __syncthreads();
    ull acc[16][2];
    #pragma unroll
    for (int h=0;h<16;h++){ acc[h][0]=0ULL; acc[h][1]=0ULL; }
    #pragma unroll 2
    for (int si=0; si<CHUNK; si++){
        float4 xv = x4[(b*4096 + s0 + si)*256 + tid];
        ull x01 = pk2(xv.x,xv.y), x23 = pk2(xv.z,xv.w);
        #pragma unroll
        for (int h=0;h<16;h++){
            ull p = *(ull*)&spm[h*128+si];
            ffma2(acc[h][0], p, x01);
            ffma2(acc[h][1], p, x23);
        }
    }
    float4* p4 = (float4*)g_partial;
    #pragma unroll
    for (int h=0;h<16;h++){
        float2 lo = upk(acc[h][0]), hi = upk(acc[h][1]);
        p4[((b*32+chunk)*16 + h)*256 + tid] = make_float4(lo.x,lo.y,hi.x,hi.y);
    }
}

// ---------------- K3r: deterministic reduction of ctx partials ----------------
__global__ void __launch_bounds__(256) k_ctxr(){
    int idx = blockIdx.x*256 + threadIdx.x;   // b*16384 + (h*1024+e)
    int b = idx>>14, rem = idx & 16383;
    float s=0.f;
    #pragma unroll
    for (int c=0;c<32;c++) s += g_partial[((b*32+c)<<14) + rem];
    g_ctx[idx] = s;
}

// ---------------- K4a: hidden = Wv·ctx + bv*psum ----------------
__global__ void __launch_bounds__(256) k_hidden(const float4* __restrict__ Wv4,
                                                const float*  __restrict__ bv){
    int lane = threadIdx.x&31, warp = threadIdx.x>>5;
    int row = blockIdx.x*8+warp;
    int h = row>>6;
    float4 w[8];
    #pragma unroll
    for (int k=0;k<8;k++) w[k] = Wv4[row*256 + lane + 32*k];
    const float4* c4 = (const float4*)g_ctx;
    float acc[8];
    #pragma unroll
    for (int b=0;b<8;b++){
        float s=0.f;
        #pragma unroll
        for (int k=0;k<8;k++){
            float4 c = c4[((b<<4)+h)*256 + lane + 32*k];
            s += w[k].x*c.x + w[k].y*c.y + w[k].z*c.z + w[k].w*c.w;
        }
        acc[b]=s;
    }
    #pragma unroll
    for (int o=16;o;o>>=1)
        #pragma unroll
        for (int b=0;b<8;b++) acc[b] += __shfl_xor_sync(0xffffffffu, acc[b], o);
    if (lane==0){
        float bvr = bv[row];
        #pragma unroll
        for (int b=0;b<8;b++) g_hidden[b*1024+row] = acc[b] + bvr*g_psum[(b<<4)+h];
    }
}

// ---------------- K4b: LayerNorm (biased var, eps=1e-5) ----------------
__global__ void __launch_bounds__(256) k_ln(const float* __restrict__ lg,
                                            const float* __restrict__ lb){
    __shared__ float red[8]; __shared__ float bc;
    int b = blockIdx.x, tid = threadIdx.x, lane=tid&31, warp=tid>>5;
    float v[4];
    #pragma unroll
    for (int j=0;j<4;j++) v[j] = g_hidden[b*1024 + tid + 256*j];
    float s = v[0]+v[1]+v[2]+v[3];
    s = warp_sum(s); if (lane==0) red[warp]=s; __syncthreads();
    if (tid==0){ float t=0.f; for(int i=0;i<8;i++)t+=red[i]; bc=t*(1.f/1024.f);} __syncthreads();
    float mu = bc;
    float q=0.f;
    #pragma unroll
    for (int j=0;j<4;j++){ float d=v[j]-mu; q+=d*d; }
    q = warp_sum(q); if(lane==0) red[warp]=q; __syncthreads();
    if (tid==0){ float t=0.f; for(int i=0;i<8;i++)t+=red[i]; bc=rsqrtf(t*(1.f/1024.f)+1e-5f);} __syncthreads();
    float rstd = bc;
    #pragma unroll
    for (int j=0;j<4;j++){
        int i = tid+256*j;
        g_hl[b*1024+i] = (v[j]-mu)*rstd*lg[i] + lb[i];
    }
}

// ---------------- K4c: act = relu(hl @ W1^T + b1) ----------------
__global__ void __launch_bounds__(256) k_mlp1(const float4* __restrict__ W14,
                                              const float*  __restrict__ b1){
    __shared__ float4 hls[2048];   // 8x1024 floats
    int tid = threadIdx.x, lane=tid&31, warp=tid>>5;
    const float4* h4 = (const float4*)g_hl;
    #pragma unroll
    for (int i=0;i<8;i++) hls[tid + 256*i] = h4[tid+256*i];
    __syncthreads();
    int row = blockIdx.x*8+warp;
    float4 w[8];
    #pragma unroll
    for (int k=0;k<8;k++) w[k]=W14[row*256+lane+32*k];
    float acc[8];
    #pragma unroll
    for (int b=0;b<8;b++){
        float s=0.f;
        #pragma unroll
        for (int k=0;k<8;k++){
            float4 hv = hls[b*256 + lane + 32*k];
            s += w[k].x*hv.x + w[k].y*hv.y + w[k].z*hv.z + w[k].w*hv.w;
        }
        acc[b]=s;
    }
    #pragma unroll
    for (int o=16;o;o>>=1)
        #pragma unroll
        for (int b=0;b<8;b++) acc[b] += __shfl_xor_sync(0xffffffffu, acc[b], o);
    if (lane==0){
        float bb = b1[row];
        #pragma unroll
        for (int b=0;b<8;b++) g_act[b*4096+row] = fmaxf(acc[b]+bb, 0.f);
    }
}

// ---------------- K4d: out = act @ W2^T + b2 ----------------
__global__ void __launch_bounds__(256) k_mlp2(const float4* __restrict__ W24,
                                              const float*  __restrict__ b2,
                                              float* __restrict__ out){
    extern __shared__ float4 as4[];    // 8x4096 floats = 128KB dynamic
    int tid=threadIdx.x, lane=tid&31, warp=tid>>5;
    const float4* a4 = (const float4*)g_act;
    #pragma unroll
    for (int i=0;i<32;i++) as4[tid+256*i] = a4[tid+256*i];
    __syncthreads();
    int row = blockIdx.x*8+warp;
    float acc[8];
    #pragma unroll
    for (int b=0;b<8;b++) acc[b]=0.f;
    #pragma unroll 4
    for (int k=0;k<32;k++){
        float4 w = W24[row*1024 + lane + 32*k];
        #pragma unroll
        for (int b=0;b<8;b++){
            float4 av = as4[b*1024 + lane + 32*k];
            acc[b] += w.x*av.x + w.y*av.y + w.z*av.z + w.w*av.w;
        }
    }
    #pragma unroll
    for (int o=16;o;o>>=1)
        #pragma unroll
        for (int b=0;b<8;b++) acc[b] += __shfl_xor_sync(0xffffffffu, acc[b], o);
    if (lane==0){
        float bb = b2[row];
        #pragma unroll
        for (int b=0;b<8;b++) out[b*1024+row] = acc[b] + bb;
    }
}

extern "C" void kernel_launch(void* const* d_in, const int* in_sizes, int n_in,
                              void* d_out, int out_size){
    const float* x     = (const float*)d_in[0];
    const float* gu    = (const float*)d_in[1];
    const float* query = (const float*)d_in[2];
    const float* Wq    = (const float*)d_in[3];
    const float* bq    = (const float*)d_in[4];
    const float* Wk    = (const float*)d_in[5];
    const float* bk    = (const float*)d_in[6];
    const float* Wv    = (const float*)d_in[7];
    const float* bv    = (const float*)d_in[8];
    const float* ln_g  = (const float*)d_in[9];
    const float* ln_b  = (const float*)d_in[10];
    const float* W1    = (const float*)d_in[11];
    const float* b1    = (const float*)d_in[12];
    const float* W2    = (const float*)d_in[13];
    const float* b2    = (const float*)d_in[14];
    float* out = (float*)d_out;

    cudaFuncSetAttribute(k_mlp2, cudaFuncAttributeMaxDynamicSharedMemorySize, 131072);

    k_wqk    <<<16,256>>>((const float4*)Wq, (const float4*)query, bq,
                          (const float4*)Wk, bk);
    k_logits <<<1024,256>>>((const float4*)x);
    k_softmax<<<128,256>>>((const float2*)gu);
    k_sums   <<<256,256>>>(out);
    k_ctx    <<<256,256>>>((const float4*)x);
    k_ctxr   <<<512,256>>>();
    k_hidden <<<128,256>>>((const float4*)Wv, bv);
    k_ln     <<<8,256>>>(ln_g, ln_b);
    k_mlp1   <<<512,256>>>((const float4*)W1, b1);
    k_mlp2   <<<128,256,131072>>>((const float4*)W2, b2, out);
}